// round 14
// baseline (speedup 1.0000x reference)
#include <cuda_runtime.h>
#include <cuda_fp16.h>
#include <cstdint>

#define NIMG 4
#define CIN  256
#define HW   16384
#define MLP  128
#define NATT 16
#define NBIN 64
#define BP   64      // pixels per block (fused kernel)

#define SX   72      // halves stride, x tile [CIN][BP]    (36 words % 32 == 4 -> conflict-free)
#define SW1  264     // halves stride, w1 [MLP][CIN]
#define SW2  136     // halves stride, w2 [NATT][MLP]
#define SH   72      // halves stride, H tile (aliases x region)
#define SAS  68      // floats stride, A tile (aliases w1 region)

#define OFF_X   0
#define OFF_W1  (CIN * SX * 2)               // 36864
#define OFF_W2  (OFF_W1 + MLP * SW1 * 2)     // 104448
#define SMEM_TOTAL (OFF_W2 + NATT * SW2 * 2) // 108800 -> 2 CTAs/SM

// C = sqrt(300 * log2(e)); exp(-300 dx^2) = 2^(-(C*dx)^2)
#define CSCALE 20.80405045f
#define INVC   0.048067556f

// device-global scratch (no runtime allocation allowed)
__device__ __half g_xh[NIMG * CIN * HW];    // 33.5 MB fp16 x
__device__ __half g_w1h[MLP * CIN];
__device__ __half g_w2h[NATT * MLP];

#define NX4   (NIMG * CIN * HW / 4)         // 4194304 float4 of x
#define NX4Q  (NX4 / 4)                     // 1048576 (4 float4 per thread)
#define NW1   (MLP * CIN / 2)               // 16384 half2
#define NW2   (NATT * MLP / 2)              // 1024 half2

// ---------------- kernel 0: fp32 -> fp16 conversion (streaming, 4x ILP) ----------------
__global__ void __launch_bounds__(256)
convert_inputs(const float* __restrict__ x,
               const float* __restrict__ w1,
               const float* __restrict__ w2) {
    int i = blockIdx.x * blockDim.x + threadIdx.x;
    if (i < NX4Q) {
        float4 v0 = __ldg((const float4*)x + i);
        float4 v1 = __ldg((const float4*)x + i + NX4Q);
        float4 v2 = __ldg((const float4*)x + i + 2 * NX4Q);
        float4 v3 = __ldg((const float4*)x + i + 3 * NX4Q);
        uint2 s0, s1, s2, s3;
        half2 h;
        h = __floats2half2_rn(v0.x, v0.y); s0.x = *(uint32_t*)&h;
        h = __floats2half2_rn(v0.z, v0.w); s0.y = *(uint32_t*)&h;
        h = __floats2half2_rn(v1.x, v1.y); s1.x = *(uint32_t*)&h;
        h = __floats2half2_rn(v1.z, v1.w); s1.y = *(uint32_t*)&h;
        h = __floats2half2_rn(v2.x, v2.y); s2.x = *(uint32_t*)&h;
        h = __floats2half2_rn(v2.z, v2.w); s2.y = *(uint32_t*)&h;
        h = __floats2half2_rn(v3.x, v3.y); s3.x = *(uint32_t*)&h;
        h = __floats2half2_rn(v3.z, v3.w); s3.y = *(uint32_t*)&h;
        *(uint2*)&g_xh[4 * i]              = s0;
        *(uint2*)&g_xh[4 * (i + NX4Q)]     = s1;
        *(uint2*)&g_xh[4 * (i + 2 * NX4Q)] = s2;
        *(uint2*)&g_xh[4 * (i + 3 * NX4Q)] = s3;
    } else {
        int j = i - NX4Q;
        if (j < NW1) {
            float2 v = __ldg((const float2*)w1 + j);
            *(half2*)&g_w1h[2 * j] = __floats2half2_rn(v.x, v.y);
        } else if (j < NW1 + NW2) {
            int k = j - NW1;
            float2 v = __ldg((const float2*)w2 + k);
            *(half2*)&g_w2h[2 * k] = __floats2half2_rn(v.x, v.y);
        }
    }
}

__device__ __forceinline__ uint32_t smem_u32(const void* p) {
    return (uint32_t)__cvta_generic_to_shared(p);
}
__device__ __forceinline__ void cpa16(uint32_t dst, const void* src) {
    asm volatile("cp.async.ca.shared.global [%0], [%1], 16;" :: "r"(dst), "l"(src));
}
__device__ __forceinline__ void ldsm4(uint32_t* r, uint32_t a) {
    asm volatile("ldmatrix.sync.aligned.m8n8.x4.shared.b16 {%0,%1,%2,%3}, [%4];"
                 : "=r"(r[0]), "=r"(r[1]), "=r"(r[2]), "=r"(r[3]) : "r"(a));
}
__device__ __forceinline__ void ldsm4t(uint32_t& r0, uint32_t& r1, uint32_t& r2, uint32_t& r3, uint32_t a) {
    asm volatile("ldmatrix.sync.aligned.m8n8.x4.trans.shared.b16 {%0,%1,%2,%3}, [%4];"
                 : "=r"(r0), "=r"(r1), "=r"(r2), "=r"(r3) : "r"(a));
}
__device__ __forceinline__ void mma16816(float* c, const uint32_t* a, uint32_t b0, uint32_t b1) {
    asm volatile("mma.sync.aligned.m16n8k16.row.col.f32.f16.f16.f32 "
                 "{%0,%1,%2,%3}, {%4,%5,%6,%7}, {%8,%9}, {%0,%1,%2,%3};"
                 : "+f"(c[0]), "+f"(c[1]), "+f"(c[2]), "+f"(c[3])
                 : "r"(a[0]), "r"(a[1]), "r"(a[2]), "r"(a[3]), "r"(b0), "r"(b1));
}
__device__ __forceinline__ float softplus_f(float v) {
    return fmaxf(v, 0.0f) + log1pf(__expf(-fabsf(v)));
}

// ---------------- kernel 1: fused MLP head + attractor update ----------------
// BP=64 px/CTA, 108.8KB smem -> 2 CTAs/SM. Attractor phase runs on fma/MUFU
// pipes, overlapping the co-resident CTA's tensor-pipe GEMM phase.
__global__ void __launch_bounds__(256, 2)
zoe_fused_kernel(const float* __restrict__ b1,
                 const float* __restrict__ b2,
                 const float* __restrict__ b_prev,
                 float* __restrict__ outp) {
    extern __shared__ char smem[];
    __half* sx  = (__half*)(smem + OFF_X);
    __half* sw1 = (__half*)(smem + OFF_W1);
    __half* sw2 = (__half*)(smem + OFF_W2);
    __half* sH  = sx;                       // H tile [128][SH] aliases x region
    float*  sA  = (float*)(smem + OFF_W1);  // A tile [16][SAS] aliases w1 region

    const int tid = threadIdx.x;
    const int blk = blockIdx.x;             // 0..1023
    const int n   = blk >> 8;               // image
    const int p0  = (blk & 255) * BP;       // pixel tile start

    // ---- stage x / w1 / w2 with cp.async (fire-and-forget, 16B chunks) ----
    {
        const uint32_t sxb = smem_u32(sx);
        const __half* xb = g_xh + (size_t)n * CIN * HW + p0;
        #pragma unroll 4
        for (int i = tid; i < CIN * 8; i += 256) {        // 64 halves/row = 8 chunks
            int c = i >> 3, ch = i & 7;
            cpa16(sxb + (uint32_t)(c * (SX * 2) + ch * 16), xb + (size_t)c * HW + ch * 8);
        }
        const uint32_t sw1b = smem_u32(sw1);
        #pragma unroll 4
        for (int i = tid; i < MLP * 32; i += 256) {       // 256 halves/row = 32 chunks
            int m = i >> 5, ch = i & 31;
            cpa16(sw1b + (uint32_t)(m * (SW1 * 2) + ch * 16), g_w1h + m * CIN + ch * 8);
        }
        const uint32_t sw2b = smem_u32(sw2);
        for (int i = tid; i < NATT * 16; i += 256) {      // 128 halves/row = 16 chunks
            int m = i >> 4, ch = i & 15;
            cpa16(sw2b + (uint32_t)(m * (SW2 * 2) + ch * 16), g_w2h + m * MLP + ch * 8);
        }
        asm volatile("cp.async.commit_group;");
        asm volatile("cp.async.wait_group 0;");
    }
    __syncthreads();

    const int warp = tid >> 5, lane = tid & 31;
    const int gid = lane >> 2, tig = lane & 3;

    // GEMM1: H = relu(W1 * X + b1);  warp tile 32m x 32p (4 m-warps x 2 n-warps)
    const int m0 = (warp >> 1) * 32;
    const int n0 = (warp & 1) * 32;

    float acc[2][4][4];
    #pragma unroll
    for (int mi = 0; mi < 2; mi++)
        #pragma unroll
        for (int nt = 0; nt < 4; nt++)
            #pragma unroll
            for (int q = 0; q < 4; q++) acc[mi][nt][q] = 0.0f;

    const uint32_t aBase = smem_u32(sw1) + (uint32_t)(((m0 + (lane & 15)) * SW1 + 8 * (lane >> 4)) * 2);
    const uint32_t bBase = smem_u32(sx)  + (uint32_t)(((((lane & 7) + 8 * ((lane >> 3) & 1)) * SX) + n0 + 8 * (lane >> 4)) * 2);

    #pragma unroll
    for (int kt = 0; kt < 16; kt++) {
        const int k0 = kt * 16;
        uint32_t a[2][4];
        ldsm4(a[0], aBase + (uint32_t)(k0 * 2));
        ldsm4(a[1], aBase + (uint32_t)((16 * SW1 + k0) * 2));
        uint32_t bf[4][2];
        #pragma unroll
        for (int nb4 = 0; nb4 < 2; nb4++) {
            uint32_t r0, r1, r2, r3;
            ldsm4t(r0, r1, r2, r3, bBase + (uint32_t)((k0 * SX + 16 * nb4) * 2));
            bf[2 * nb4][0] = r0; bf[2 * nb4][1] = r1;
            bf[2 * nb4 + 1][0] = r2; bf[2 * nb4 + 1][1] = r3;
        }
        #pragma unroll
        for (int mi = 0; mi < 2; mi++)
            #pragma unroll
            for (int nt = 0; nt < 4; nt++)
                mma16816(acc[mi][nt], a[mi], bf[nt][0], bf[nt][1]);
    }
    __syncthreads();

    // epilogue 1: bias + relu -> fp16 H
    #pragma unroll
    for (int mi = 0; mi < 2; mi++) {
        const int r = m0 + 16 * mi + gid;
        const float bb0 = __ldg(b1 + r);
        const float bb1 = __ldg(b1 + r + 8);
        #pragma unroll
        for (int nt = 0; nt < 4; nt++) {
            const int col = n0 + 8 * nt + 2 * tig;
            float v0 = fmaxf(acc[mi][nt][0] + bb0, 0.0f);
            float v1 = fmaxf(acc[mi][nt][1] + bb0, 0.0f);
            float v2 = fmaxf(acc[mi][nt][2] + bb1, 0.0f);
            float v3 = fmaxf(acc[mi][nt][3] + bb1, 0.0f);
            *(half2*)&sH[r * SH + col]       = __floats2half2_rn(v0, v1);
            *(half2*)&sH[(r + 8) * SH + col] = __floats2half2_rn(v2, v3);
        }
    }
    __syncthreads();

    // GEMM2: A = C * softplus(W2 * H + b2); warps 0-3 each do 16a x 16p
    if (warp < 4) {
        const int n0b = 16 * warp;
        float acc2[2][4] = {{0.f,0.f,0.f,0.f},{0.f,0.f,0.f,0.f}};
        const uint32_t aB2 = smem_u32(sw2) + (uint32_t)((((lane & 15) * SW2) + 8 * (lane >> 4)) * 2);
        const uint32_t bB2 = smem_u32(sH)  + (uint32_t)(((((lane & 7) + 8 * ((lane >> 3) & 1)) * SH) + n0b + 8 * (lane >> 4)) * 2);
        #pragma unroll
        for (int kk = 0; kk < 8; kk++) {
            uint32_t a2r[4];
            ldsm4(a2r, aB2 + (uint32_t)(16 * kk * 2));
            uint32_t r0, r1, r2, r3;
            ldsm4t(r0, r1, r2, r3, bB2 + (uint32_t)(16 * kk * SH * 2));
            mma16816(acc2[0], a2r, r0, r1);
            mma16816(acc2[1], a2r, r2, r3);
        }
        const float bb0 = __ldg(b2 + gid);
        const float bb1 = __ldg(b2 + gid + 8);
        #pragma unroll
        for (int s = 0; s < 2; s++) {
            const int colb = n0b + 8 * s + 2 * tig;
            sA[gid * SAS + colb]           = CSCALE * softplus_f(acc2[s][0] + bb0);
            sA[gid * SAS + colb + 1]       = CSCALE * softplus_f(acc2[s][1] + bb0);
            sA[(gid + 8) * SAS + colb]     = CSCALE * softplus_f(acc2[s][2] + bb1);
            sA[(gid + 8) * SAS + colb + 1] = CSCALE * softplus_f(acc2[s][3] + bb1);
        }
    }
    __syncthreads();

    // ---- attractor phase: out = b + sum_a exp(-300 dx^2) * dx, f16x2 packed ----
    {
        const int pr = tid & 31;        // pixel pair 0..31 within tile
        const int g  = tid >> 5;        // bin group 0..7 -> bins [8g, 8g+8)

        float a0[NATT], a1[NATT];       // C-scaled A for both pixels of the pair
        #pragma unroll
        for (int a = 0; a < NATT; a++) {
            float2 v = *(const float2*)&sA[a * SAS + 2 * pr];
            a0[a] = v.x; a1[a] = v.y;
        }

        const size_t base = ((size_t)n * NBIN + g * 8) * HW + p0 + 2 * pr;
        const float2* bp = (const float2*)(b_prev + base);
        float2* o1 = (float2*)(outp + base);
        float2* o2 = (float2*)(outp + base + (size_t)NIMG * NBIN * HW);

        #pragma unroll 2
        for (int j = 0; j < 8; j++) {
            const size_t off = (size_t)j * (HW / 2);
            const float2 b = __ldg(bp + off);
            const float cb0 = CSCALE * b.x;
            const float cb1 = CSCALE * b.y;

            __half2 accA = __floats2half2_rn(0.0f, 0.0f);
            __half2 accB = accA;
            #pragma unroll
            for (int a = 0; a < NATT; a += 2) {
                {
                    float u0 = a0[a] - cb0;
                    float u1 = a1[a] - cb1;
                    __half2 u2 = __floats2half2_rn(u0, u1);
                    __half2 y2 = __hneg2(__hmul2(u2, u2));
                    uint32_t uy = *(uint32_t*)&y2, ue;
                    asm("ex2.approx.f16x2 %0, %1;" : "=r"(ue) : "r"(uy));
                    accA = __hfma2(*(__half2*)&ue, u2, accA);
                }
                {
                    float u0 = a0[a + 1] - cb0;
                    float u1 = a1[a + 1] - cb1;
                    __half2 u2 = __floats2half2_rn(u0, u1);
                    __half2 y2 = __hneg2(__hmul2(u2, u2));
                    uint32_t uy = *(uint32_t*)&y2, ue;
                    asm("ex2.approx.f16x2 %0, %1;" : "=r"(ue) : "r"(uy));
                    accB = __hfma2(*(__half2*)&ue, u2, accB);
                }
            }
            float s0 = __low2float(accA)  + __low2float(accB);
            float s1 = __high2float(accA) + __high2float(accB);
            float2 dv;
            dv.x = fmaf(s0, INVC, b.x);
            dv.y = fmaf(s1, INVC, b.y);
            o1[off] = dv;
            o2[off] = dv;
        }
    }
}

extern "C" void kernel_launch(void* const* d_in, const int* in_sizes, int n_in,
                              void* d_out, int out_size) {
    const float* x      = (const float*)d_in[0];
    const float* b_prev = (const float*)d_in[1];
    const float* w1     = (const float*)d_in[2];
    const float* b1     = (const float*)d_in[3];
    const float* w2     = (const float*)d_in[4];
    const float* b2     = (const float*)d_in[5];
    float* out = (float*)d_out;

    const int ntot = NX4Q + NW1 + NW2;
    convert_inputs<<<(ntot + 255) / 256, 256>>>(x, w1, w2);

    cudaFuncSetAttribute(zoe_fused_kernel,
                         cudaFuncAttributeMaxDynamicSharedMemorySize, SMEM_TOTAL);
    zoe_fused_kernel<<<NIMG * (HW / BP), 256, SMEM_TOTAL>>>(b1, b2, b_prev, out);
}

// round 15
// speedup vs baseline: 1.1995x; 1.1995x over previous
#include <cuda_runtime.h>
#include <cuda_fp16.h>
#include <cstdint>

#define NIMG 4
#define CIN  256
#define HW   16384
#define MLP  128
#define NATT 16
#define NBIN 64
#define BP   64      // pixels per block (MLP kernel)

#define SX   72      // halves stride, x tile [CIN][BP]    (36 words % 32 == 4 -> conflict-free)
#define SW1  264     // halves stride, w1 [MLP][CIN]
#define SW2  136     // halves stride, w2 [NATT][MLP]
#define SH   72      // halves stride, H tile (aliases x region)
#define SAS  68      // floats stride, A tile (aliases w1 region)

#define OFF_X   0
#define OFF_W1  (CIN * SX * 2)               // 36864
#define OFF_W2  (OFF_W1 + MLP * SW1 * 2)     // 104448
#define SMEM_TOTAL (OFF_W2 + NATT * SW2 * 2) // 108800 -> 2 CTAs/SM

// C = sqrt(300 * log2(e)); exp(-300 dx^2) = 2^(-(C*dx)^2)
#define CSCALE 20.80405045f
#define INVC   0.048067556f

// device-global scratch (no runtime allocation allowed)
__device__ __half g_xh[NIMG * CIN * HW];    // 33.5 MB fp16 x
__device__ __half g_w1h[MLP * CIN];
__device__ __half g_w2h[NATT * MLP];
__device__ float  g_A[NIMG * NATT * HW];    // 4 MB, C-scaled A

#define NX4   (NIMG * CIN * HW / 4)         // 4194304 float4 of x
#define NP4   (NX4 / 8)                     // 524288: threads for x (4 slabs x 2 float4)
#define NW1   (MLP * CIN / 2)               // 16384 half2
#define NW2   (NATT * MLP / 2)              // 1024 half2

// ---------------- kernel 0: fp32 -> fp16 conversion (8 loads / 4 x 16B stores) ----------------
__global__ void __launch_bounds__(256)
convert_inputs(const float* __restrict__ x,
               const float* __restrict__ w1,
               const float* __restrict__ w2) {
    int i = blockIdx.x * blockDim.x + threadIdx.x;
    if (i < NP4) {
        #pragma unroll
        for (int s = 0; s < 4; s++) {
            const int p = i + s * NP4;                 // float4-pair index
            float4 va = __ldg((const float4*)x + 2 * p);
            float4 vb = __ldg((const float4*)x + 2 * p + 1);
            half2 h0 = __floats2half2_rn(va.x, va.y);
            half2 h1 = __floats2half2_rn(va.z, va.w);
            half2 h2 = __floats2half2_rn(vb.x, vb.y);
            half2 h3 = __floats2half2_rn(vb.z, vb.w);
            uint4 st;
            st.x = *(uint32_t*)&h0;
            st.y = *(uint32_t*)&h1;
            st.z = *(uint32_t*)&h2;
            st.w = *(uint32_t*)&h3;
            *(uint4*)&g_xh[8 * p] = st;
        }
    } else {
        int j = i - NP4;
        if (j < NW1) {
            float2 v = __ldg((const float2*)w1 + j);
            *(half2*)&g_w1h[2 * j] = __floats2half2_rn(v.x, v.y);
        } else if (j < NW1 + NW2) {
            int k = j - NW1;
            float2 v = __ldg((const float2*)w2 + k);
            *(half2*)&g_w2h[2 * k] = __floats2half2_rn(v.x, v.y);
        }
    }
}

__device__ __forceinline__ uint32_t smem_u32(const void* p) {
    return (uint32_t)__cvta_generic_to_shared(p);
}
__device__ __forceinline__ void cpa16(uint32_t dst, const void* src) {
    asm volatile("cp.async.ca.shared.global [%0], [%1], 16;" :: "r"(dst), "l"(src));
}
__device__ __forceinline__ void ldsm4(uint32_t* r, uint32_t a) {
    asm volatile("ldmatrix.sync.aligned.m8n8.x4.shared.b16 {%0,%1,%2,%3}, [%4];"
                 : "=r"(r[0]), "=r"(r[1]), "=r"(r[2]), "=r"(r[3]) : "r"(a));
}
__device__ __forceinline__ void ldsm4t(uint32_t& r0, uint32_t& r1, uint32_t& r2, uint32_t& r3, uint32_t a) {
    asm volatile("ldmatrix.sync.aligned.m8n8.x4.trans.shared.b16 {%0,%1,%2,%3}, [%4];"
                 : "=r"(r0), "=r"(r1), "=r"(r2), "=r"(r3) : "r"(a));
}
__device__ __forceinline__ void mma16816(float* c, const uint32_t* a, uint32_t b0, uint32_t b1) {
    asm volatile("mma.sync.aligned.m16n8k16.row.col.f32.f16.f16.f32 "
                 "{%0,%1,%2,%3}, {%4,%5,%6,%7}, {%8,%9}, {%0,%1,%2,%3};"
                 : "+f"(c[0]), "+f"(c[1]), "+f"(c[2]), "+f"(c[3])
                 : "r"(a[0]), "r"(a[1]), "r"(a[2]), "r"(a[3]), "r"(b0), "r"(b1));
}
__device__ __forceinline__ float softplus_f(float v) {
    return fmaxf(v, 0.0f) + log1pf(__expf(-fabsf(v)));
}

// ---------------- kernel 1: fused 1x1-conv MLP head -> scaled A scratch ----------------
// BP=64 px/CTA, 108.8KB smem -> 2 CTAs/SM. Staging pipelined in 4 K-chunks:
// GEMM1 starts after chunk 0 lands; chunks 1-3 stream in behind the MMA loop.
__global__ void __launch_bounds__(256, 2)
zoe_mlp_kernel(const float* __restrict__ b1,
               const float* __restrict__ b2) {
    extern __shared__ char smem[];
    __half* sx  = (__half*)(smem + OFF_X);
    __half* sw1 = (__half*)(smem + OFF_W1);
    __half* sw2 = (__half*)(smem + OFF_W2);
    __half* sH  = sx;                       // H tile [128][SH] aliases x region
    float*  sA  = (float*)(smem + OFF_W1);  // A tile [16][SAS] aliases w1 region

    const int tid = threadIdx.x;
    const int blk = blockIdx.x;             // 0..1023
    const int n   = blk >> 8;               // image
    const int p0  = (blk & 255) * BP;       // pixel tile start

    // ---- issue all staging as 4 K-chunk commit groups (fire-and-forget) ----
    {
        const uint32_t sxb  = smem_u32(sx);
        const uint32_t sw1b = smem_u32(sw1);
        const uint32_t sw2b = smem_u32(sw2);
        const __half* xb = g_xh + (size_t)n * CIN * HW + p0;

        #pragma unroll
        for (int kc = 0; kc < 4; kc++) {
            const int c0 = 64 * kc;
            // x channels [c0, c0+64), 64 halves/row = 8 chunks
            for (int i = tid; i < 64 * 8; i += 256) {
                int c = c0 + (i >> 3), ch = i & 7;
                cpa16(sxb + (uint32_t)(c * (SX * 2) + ch * 16), xb + (size_t)c * HW + ch * 8);
            }
            // w1 k-cols [c0, c0+64) for all 128 m-rows, 8 chunks/row
            for (int i = tid; i < MLP * 8; i += 256) {
                int m = i >> 3, ch = i & 7;
                cpa16(sw1b + (uint32_t)(m * (SW1 * 2) + c0 * 2 + ch * 16),
                      g_w1h + m * CIN + c0 + ch * 8);
            }
            if (kc == 3) {
                // w2: 128 halves/row = 16 chunks, 16 rows
                for (int i = tid; i < NATT * 16; i += 256) {
                    int m = i >> 4, ch = i & 15;
                    cpa16(sw2b + (uint32_t)(m * (SW2 * 2) + ch * 16), g_w2h + m * MLP + ch * 8);
                }
            }
            asm volatile("cp.async.commit_group;");
        }
    }

    const int warp = tid >> 5, lane = tid & 31;
    const int gid = lane >> 2, tig = lane & 3;

    // GEMM1: H = relu(W1 * X + b1);  warp tile 32m x 32p (4 m-warps x 2 n-warps)
    const int m0 = (warp >> 1) * 32;
    const int n0 = (warp & 1) * 32;

    float acc[2][4][4];
    #pragma unroll
    for (int mi = 0; mi < 2; mi++)
        #pragma unroll
        for (int nt = 0; nt < 4; nt++)
            #pragma unroll
            for (int q = 0; q < 4; q++) acc[mi][nt][q] = 0.0f;

    const uint32_t aBase = smem_u32(sw1) + (uint32_t)(((m0 + (lane & 15)) * SW1 + 8 * (lane >> 4)) * 2);
    const uint32_t bBase = smem_u32(sx)  + (uint32_t)(((((lane & 7) + 8 * ((lane >> 3) & 1)) * SX) + n0 + 8 * (lane >> 4)) * 2);

    #pragma unroll
    for (int kc = 0; kc < 4; kc++) {
        // wait for chunk kc (groups 0..kc complete -> <= 3-kc outstanding)
        if (kc == 0)      asm volatile("cp.async.wait_group 3;");
        else if (kc == 1) asm volatile("cp.async.wait_group 2;");
        else if (kc == 2) asm volatile("cp.async.wait_group 1;");
        else              asm volatile("cp.async.wait_group 0;");
        __syncthreads();

        #pragma unroll
        for (int kt = 4 * kc; kt < 4 * kc + 4; kt++) {
            const int k0 = kt * 16;
            uint32_t a[2][4];
            ldsm4(a[0], aBase + (uint32_t)(k0 * 2));
            ldsm4(a[1], aBase + (uint32_t)((16 * SW1 + k0) * 2));
            uint32_t bf[4][2];
            #pragma unroll
            for (int nb4 = 0; nb4 < 2; nb4++) {
                uint32_t r0, r1, r2, r3;
                ldsm4t(r0, r1, r2, r3, bBase + (uint32_t)((k0 * SX + 16 * nb4) * 2));
                bf[2 * nb4][0] = r0; bf[2 * nb4][1] = r1;
                bf[2 * nb4 + 1][0] = r2; bf[2 * nb4 + 1][1] = r3;
            }
            #pragma unroll
            for (int mi = 0; mi < 2; mi++)
                #pragma unroll
                for (int nt = 0; nt < 4; nt++)
                    mma16816(acc[mi][nt], a[mi], bf[nt][0], bf[nt][1]);
        }
    }
    __syncthreads();

    // epilogue 1: bias + relu -> fp16 H
    #pragma unroll
    for (int mi = 0; mi < 2; mi++) {
        const int r = m0 + 16 * mi + gid;
        const float bb0 = __ldg(b1 + r);
        const float bb1 = __ldg(b1 + r + 8);
        #pragma unroll
        for (int nt = 0; nt < 4; nt++) {
            const int col = n0 + 8 * nt + 2 * tig;
            float v0 = fmaxf(acc[mi][nt][0] + bb0, 0.0f);
            float v1 = fmaxf(acc[mi][nt][1] + bb0, 0.0f);
            float v2 = fmaxf(acc[mi][nt][2] + bb1, 0.0f);
            float v3 = fmaxf(acc[mi][nt][3] + bb1, 0.0f);
            *(half2*)&sH[r * SH + col]       = __floats2half2_rn(v0, v1);
            *(half2*)&sH[(r + 8) * SH + col] = __floats2half2_rn(v2, v3);
        }
    }
    __syncthreads();

    // GEMM2: A = softplus(W2 * H + b2); warps 0-3 each do 16a x 16p
    if (warp < 4) {
        const int n0b = 16 * warp;
        float acc2[2][4] = {{0.f,0.f,0.f,0.f},{0.f,0.f,0.f,0.f}};
        const uint32_t aB2 = smem_u32(sw2) + (uint32_t)((((lane & 15) * SW2) + 8 * (lane >> 4)) * 2);
        const uint32_t bB2 = smem_u32(sH)  + (uint32_t)(((((lane & 7) + 8 * ((lane >> 3) & 1)) * SH) + n0b + 8 * (lane >> 4)) * 2);
        #pragma unroll
        for (int kk = 0; kk < 8; kk++) {
            uint32_t a2r[4];
            ldsm4(a2r, aB2 + (uint32_t)(16 * kk * 2));
            uint32_t r0, r1, r2, r3;
            ldsm4t(r0, r1, r2, r3, bB2 + (uint32_t)(16 * kk * SH * 2));
            mma16816(acc2[0], a2r, r0, r1);
            mma16816(acc2[1], a2r, r2, r3);
        }
        const float bb0 = __ldg(b2 + gid);
        const float bb1 = __ldg(b2 + gid + 8);
        #pragma unroll
        for (int s = 0; s < 2; s++) {
            const int colb = n0b + 8 * s + 2 * tig;
            sA[gid * SAS + colb]           = softplus_f(acc2[s][0] + bb0);
            sA[gid * SAS + colb + 1]       = softplus_f(acc2[s][1] + bb0);
            sA[(gid + 8) * SAS + colb]     = softplus_f(acc2[s][2] + bb1);
            sA[(gid + 8) * SAS + colb + 1] = softplus_f(acc2[s][3] + bb1);
        }
    }
    __syncthreads();

    // write C-scaled A tile coalesced: g_A[n][a][px] = C * A
    {
        float* Ag = g_A + (size_t)n * NATT * HW + p0;
        #pragma unroll
        for (int i = tid; i < NATT * BP; i += 256) {
            int a = i >> 6, p = i & 63;
            Ag[(size_t)a * HW + p] = CSCALE * sA[a * SAS + p];
        }
    }
}

// ---------------- kernel 2: attractor update, f16x2 packed, grid=1024 ----------------
__global__ void __launch_bounds__(256)
zoe_attractor_kernel(const float* __restrict__ b_prev, float* __restrict__ out) {
    const int blk = blockIdx.x;          // 1024 blocks: 128-px tile x 32-bin half
    const int n   = blk >> 8;
    const int t   = (blk >> 1) & 127;    // pixel tile
    const int h   = blk & 1;             // bin half: [32h, 32h+32)
    const int p0  = t * 128;
    const int pr  = threadIdx.x & 63;    // pixel pair within tile
    const int q   = threadIdx.x >> 6;    // 8-bin group within half
    const int px  = p0 + 2 * pr;

    const float2* Ap = (const float2*)(g_A + (size_t)n * NATT * HW + px);
    float a0[NATT], a1[NATT];
    #pragma unroll
    for (int a = 0; a < NATT; a++) {
        float2 v = __ldg(Ap + (size_t)a * (HW / 2));
        a0[a] = v.x; a1[a] = v.y;
    }

    const size_t base = ((size_t)n * NBIN + h * 32 + q * 8) * HW + px;
    const float2* bp = (const float2*)(b_prev + base);
    float2* o1 = (float2*)(out + base);
    float2* o2 = (float2*)(out + base + (size_t)NIMG * NBIN * HW);

    #pragma unroll 2
    for (int j = 0; j < 8; j++) {
        const size_t off = (size_t)j * (HW / 2);
        const float2 b = __ldg(bp + off);
        const float cb0 = CSCALE * b.x;
        const float cb1 = CSCALE * b.y;

        __half2 accA = __floats2half2_rn(0.0f, 0.0f);
        __half2 accB = accA;
        #pragma unroll
        for (int a = 0; a < NATT; a += 2) {
            {
                float u0 = a0[a] - cb0;
                float u1 = a1[a] - cb1;
                __half2 u2 = __floats2half2_rn(u0, u1);
                __half2 y2 = __hneg2(__hmul2(u2, u2));
                uint32_t uy = *(uint32_t*)&y2, ue;
                asm("ex2.approx.f16x2 %0, %1;" : "=r"(ue) : "r"(uy));
                accA = __hfma2(*(__half2*)&ue, u2, accA);
            }
            {
                float u0 = a0[a + 1] - cb0;
                float u1 = a1[a + 1] - cb1;
                __half2 u2 = __floats2half2_rn(u0, u1);
                __half2 y2 = __hneg2(__hmul2(u2, u2));
                uint32_t uy = *(uint32_t*)&y2, ue;
                asm("ex2.approx.f16x2 %0, %1;" : "=r"(ue) : "r"(uy));
                accB = __hfma2(*(__half2*)&ue, u2, accB);
            }
        }
        float s0 = __low2float(accA)  + __low2float(accB);
        float s1 = __high2float(accA) + __high2float(accB);
        float2 dv;
        dv.x = fmaf(s0, INVC, b.x);
        dv.y = fmaf(s1, INVC, b.y);
        o1[off] = dv;
        o2[off] = dv;
    }
}

extern "C" void kernel_launch(void* const* d_in, const int* in_sizes, int n_in,
                              void* d_out, int out_size) {
    const float* x      = (const float*)d_in[0];
    const float* b_prev = (const float*)d_in[1];
    const float* w1     = (const float*)d_in[2];
    const float* b1     = (const float*)d_in[3];
    const float* w2     = (const float*)d_in[4];
    const float* b2     = (const float*)d_in[5];
    float* out = (float*)d_out;

    const int ntot = NP4 + NW1 + NW2;
    convert_inputs<<<(ntot + 255) / 256, 256>>>(x, w1, w2);

    cudaFuncSetAttribute(zoe_mlp_kernel,
                         cudaFuncAttributeMaxDynamicSharedMemorySize, SMEM_TOTAL);
    zoe_mlp_kernel<<<NIMG * (HW / BP), 256, SMEM_TOTAL>>>(b1, b2);

    zoe_attractor_kernel<<<NIMG * 256, 256>>>(b_prev, out);
}

// round 17
// speedup vs baseline: 1.2834x; 1.0699x over previous
#include <cuda_runtime.h>
#include <cuda_fp16.h>
#include <cstdint>

#define NIMG 4
#define CIN  256
#define HW   16384
#define MLP  128
#define NATT 16
#define NBIN 64
#define BP   64      // pixels per block (MLP kernel)

#define SX   72      // halves stride, x tile [CIN][BP]    (36 words % 32 == 4 -> conflict-free)
#define SW1  264     // halves stride, w1 [MLP][CIN]
#define SW2  136     // halves stride, w2 [NATT][MLP]
#define SH   72      // halves stride, H tile (aliases x region)
#define SAS  68      // floats stride, A tile (aliases w1 region)

#define OFF_X   0
#define OFF_W1  (CIN * SX * 2)               // 36864
#define OFF_W2  (OFF_W1 + MLP * SW1 * 2)     // 104448
#define SMEM_TOTAL (OFF_W2 + NATT * SW2 * 2) // 108800 -> 2 CTAs/SM

// C = sqrt(300 * log2(e)); exp(-300 dx^2) = 2^(-(C*dx)^2)
#define CSCALE 20.80405045f
#define INVC   0.048067556f

// device-global scratch (no runtime allocation allowed)
__device__ __half g_xh[NIMG * CIN * HW];    // 33.5 MB fp16 x
__device__ __half g_w1h[MLP * CIN];
__device__ __half g_w2h[NATT * MLP];
__device__ float  g_A[NIMG * NATT * HW];    // 4 MB, C-scaled A

#define NX4   (NIMG * CIN * HW / 4)         // 4194304 float4 of x
#define NX4Q  (NX4 / 4)                     // 1048576 (4 float4 per thread)
#define NW1   (MLP * CIN / 2)               // 16384 half2
#define NW2   (NATT * MLP / 2)              // 1024 half2

// ---------------- kernel 0: fp32 -> fp16 conversion (streaming, 4x ILP) ----------------
__global__ void __launch_bounds__(256)
convert_inputs(const float* __restrict__ x,
               const float* __restrict__ w1,
               const float* __restrict__ w2) {
    // allow the (PDL-gated) MLP kernel to begin dispatching early; its
    // griddepcontrol.wait still blocks until this grid fully completes.
    asm volatile("griddepcontrol.launch_dependents;" ::: "memory");
    int i = blockIdx.x * blockDim.x + threadIdx.x;
    if (i < NX4Q) {
        float4 v0 = __ldcs((const float4*)x + i);
        float4 v1 = __ldcs((const float4*)x + i + NX4Q);
        float4 v2 = __ldcs((const float4*)x + i + 2 * NX4Q);
        float4 v3 = __ldcs((const float4*)x + i + 3 * NX4Q);
        uint2 s0, s1, s2, s3;
        half2 h;
        h = __floats2half2_rn(v0.x, v0.y); s0.x = *(uint32_t*)&h;
        h = __floats2half2_rn(v0.z, v0.w); s0.y = *(uint32_t*)&h;
        h = __floats2half2_rn(v1.x, v1.y); s1.x = *(uint32_t*)&h;
        h = __floats2half2_rn(v1.z, v1.w); s1.y = *(uint32_t*)&h;
        h = __floats2half2_rn(v2.x, v2.y); s2.x = *(uint32_t*)&h;
        h = __floats2half2_rn(v2.z, v2.w); s2.y = *(uint32_t*)&h;
        h = __floats2half2_rn(v3.x, v3.y); s3.x = *(uint32_t*)&h;
        h = __floats2half2_rn(v3.z, v3.w); s3.y = *(uint32_t*)&h;
        *(uint2*)&g_xh[4 * i]              = s0;
        *(uint2*)&g_xh[4 * (i + NX4Q)]     = s1;
        *(uint2*)&g_xh[4 * (i + 2 * NX4Q)] = s2;
        *(uint2*)&g_xh[4 * (i + 3 * NX4Q)] = s3;
    } else {
        int j = i - NX4Q;
        if (j < NW1) {
            float2 v = __ldg((const float2*)w1 + j);
            *(half2*)&g_w1h[2 * j] = __floats2half2_rn(v.x, v.y);
        } else if (j < NW1 + NW2) {
            int k = j - NW1;
            float2 v = __ldg((const float2*)w2 + k);
            *(half2*)&g_w2h[2 * k] = __floats2half2_rn(v.x, v.y);
        }
    }
}

__device__ __forceinline__ uint32_t smem_u32(const void* p) {
    return (uint32_t)__cvta_generic_to_shared(p);
}
__device__ __forceinline__ void cpa16(uint32_t dst, const void* src) {
    asm volatile("cp.async.ca.shared.global [%0], [%1], 16;" :: "r"(dst), "l"(src));
}
__device__ __forceinline__ void ldsm4(uint32_t* r, uint32_t a) {
    asm volatile("ldmatrix.sync.aligned.m8n8.x4.shared.b16 {%0,%1,%2,%3}, [%4];"
                 : "=r"(r[0]), "=r"(r[1]), "=r"(r[2]), "=r"(r[3]) : "r"(a));
}
__device__ __forceinline__ void ldsm4t(uint32_t& r0, uint32_t& r1, uint32_t& r2, uint32_t& r3, uint32_t a) {
    asm volatile("ldmatrix.sync.aligned.m8n8.x4.trans.shared.b16 {%0,%1,%2,%3}, [%4];"
                 : "=r"(r0), "=r"(r1), "=r"(r2), "=r"(r3) : "r"(a));
}
__device__ __forceinline__ void mma16816(float* c, const uint32_t* a, uint32_t b0, uint32_t b1) {
    asm volatile("mma.sync.aligned.m16n8k16.row.col.f32.f16.f16.f32 "
                 "{%0,%1,%2,%3}, {%4,%5,%6,%7}, {%8,%9}, {%0,%1,%2,%3};"
                 : "+f"(c[0]), "+f"(c[1]), "+f"(c[2]), "+f"(c[3])
                 : "r"(a[0]), "r"(a[1]), "r"(a[2]), "r"(a[3]), "r"(b0), "r"(b1));
}
__device__ __forceinline__ float softplus_f(float v) {
    return fmaxf(v, 0.0f) + log1pf(__expf(-fabsf(v)));
}
// packed f32x2 helpers (sm_103a)
__device__ __forceinline__ uint64_t pack_f2(float lo, float hi) {
    uint64_t r; asm("mov.b64 %0, {%1, %2};" : "=l"(r) : "f"(lo), "f"(hi)); return r;
}
__device__ __forceinline__ void unpack_f2(uint64_t v, float& lo, float& hi) {
    asm("mov.b64 {%0, %1}, %2;" : "=f"(lo), "=f"(hi) : "l"(v));
}
__device__ __forceinline__ uint64_t addx2(uint64_t a, uint64_t b) {
    uint64_t r; asm("add.rn.f32x2 %0, %1, %2;" : "=l"(r) : "l"(a), "l"(b)); return r;
}
__device__ __forceinline__ uint64_t mulx2(uint64_t a, uint64_t b) {
    uint64_t r; asm("mul.rn.f32x2 %0, %1, %2;" : "=l"(r) : "l"(a), "l"(b)); return r;
}

// ---------------- kernel 1: fused 1x1-conv MLP head -> scaled A scratch ----------------
// BP=64 pixels per CTA, 108.8KB smem -> 2 CTAs/SM; all staging via cp.async.
__global__ void __launch_bounds__(256, 2)
zoe_mlp_kernel(const float* __restrict__ b1,
               const float* __restrict__ b2) {
    // trigger attractor dispatch once ALL MLP CTAs have started (tail overlap),
    // then wait for convert_inputs to finish before touching g_xh/g_w*h.
    asm volatile("griddepcontrol.launch_dependents;" ::: "memory");
    asm volatile("griddepcontrol.wait;" ::: "memory");

    extern __shared__ char smem[];
    __half* sx  = (__half*)(smem + OFF_X);
    __half* sw1 = (__half*)(smem + OFF_W1);
    __half* sw2 = (__half*)(smem + OFF_W2);
    __half* sH  = sx;                       // H tile [128][SH] aliases x region
    float*  sA  = (float*)(smem + OFF_W1);  // A tile [16][SAS] aliases w1 region

    const int tid = threadIdx.x;
    const int blk = blockIdx.x;             // 0..1023
    const int n   = blk >> 8;               // image
    const int p0  = (blk & 255) * BP;       // pixel tile start

    // ---- stage x / w1 / w2 with cp.async (fire-and-forget, 16B chunks) ----
    {
        const uint32_t sxb = smem_u32(sx);
        const __half* xb = g_xh + (size_t)n * CIN * HW + p0;
        #pragma unroll 4
        for (int i = tid; i < CIN * 8; i += 256) {        // 64 halves/row = 8 chunks
            int c = i >> 3, ch = i & 7;
            cpa16(sxb + (uint32_t)(c * (SX * 2) + ch * 16), xb + (size_t)c * HW + ch * 8);
        }
        const uint32_t sw1b = smem_u32(sw1);
        #pragma unroll 4
        for (int i = tid; i < MLP * 32; i += 256) {       // 256 halves/row = 32 chunks
            int m = i >> 5, ch = i & 31;
            cpa16(sw1b + (uint32_t)(m * (SW1 * 2) + ch * 16), g_w1h + m * CIN + ch * 8);
        }
        const uint32_t sw2b = smem_u32(sw2);
        for (int i = tid; i < NATT * 16; i += 256) {      // 128 halves/row = 16 chunks
            int m = i >> 4, ch = i & 15;
            cpa16(sw2b + (uint32_t)(m * (SW2 * 2) + ch * 16), g_w2h + m * MLP + ch * 8);
        }
        asm volatile("cp.async.commit_group;");
        asm volatile("cp.async.wait_group 0;");
    }
    __syncthreads();

    const int warp = tid >> 5, lane = tid & 31;
    const int gid = lane >> 2, tig = lane & 3;

    // GEMM1: H = relu(W1 * X + b1);  warp tile 32m x 32p (4 m-warps x 2 n-warps)
    const int m0 = (warp >> 1) * 32;
    const int n0 = (warp & 1) * 32;

    float acc[2][4][4];
    #pragma unroll
    for (int mi = 0; mi < 2; mi++)
        #pragma unroll
        for (int nt = 0; nt < 4; nt++)
            #pragma unroll
            for (int q = 0; q < 4; q++) acc[mi][nt][q] = 0.0f;

    const uint32_t aBase = smem_u32(sw1) + (uint32_t)(((m0 + (lane & 15)) * SW1 + 8 * (lane >> 4)) * 2);
    const uint32_t bBase = smem_u32(sx)  + (uint32_t)(((((lane & 7) + 8 * ((lane >> 3) & 1)) * SX) + n0 + 8 * (lane >> 4)) * 2);

    #pragma unroll
    for (int kt = 0; kt < 16; kt++) {
        const int k0 = kt * 16;
        uint32_t a[2][4];
        ldsm4(a[0], aBase + (uint32_t)(k0 * 2));
        ldsm4(a[1], aBase + (uint32_t)((16 * SW1 + k0) * 2));
        uint32_t bf[4][2];
        #pragma unroll
        for (int nb4 = 0; nb4 < 2; nb4++) {
            uint32_t r0, r1, r2, r3;
            ldsm4t(r0, r1, r2, r3, bBase + (uint32_t)((k0 * SX + 16 * nb4) * 2));
            bf[2 * nb4][0] = r0; bf[2 * nb4][1] = r1;
            bf[2 * nb4 + 1][0] = r2; bf[2 * nb4 + 1][1] = r3;
        }
        #pragma unroll
        for (int mi = 0; mi < 2; mi++)
            #pragma unroll
            for (int nt = 0; nt < 4; nt++)
                mma16816(acc[mi][nt], a[mi], bf[nt][0], bf[nt][1]);
    }
    __syncthreads();

    // epilogue 1: bias + relu -> fp16 H
    #pragma unroll
    for (int mi = 0; mi < 2; mi++) {
        const int r = m0 + 16 * mi + gid;
        const float bb0 = __ldg(b1 + r);
        const float bb1 = __ldg(b1 + r + 8);
        #pragma unroll
        for (int nt = 0; nt < 4; nt++) {
            const int col = n0 + 8 * nt + 2 * tig;
            float v0 = fmaxf(acc[mi][nt][0] + bb0, 0.0f);
            float v1 = fmaxf(acc[mi][nt][1] + bb0, 0.0f);
            float v2 = fmaxf(acc[mi][nt][2] + bb1, 0.0f);
            float v3 = fmaxf(acc[mi][nt][3] + bb1, 0.0f);
            *(half2*)&sH[r * SH + col]       = __floats2half2_rn(v0, v1);
            *(half2*)&sH[(r + 8) * SH + col] = __floats2half2_rn(v2, v3);
        }
    }
    __syncthreads();

    // GEMM2: A = softplus(W2 * H + b2); warps 0-3 each do 16a x 16p
    if (warp < 4) {
        const int n0b = 16 * warp;
        float acc2[2][4] = {{0.f,0.f,0.f,0.f},{0.f,0.f,0.f,0.f}};
        const uint32_t aB2 = smem_u32(sw2) + (uint32_t)((((lane & 15) * SW2) + 8 * (lane >> 4)) * 2);
        const uint32_t bB2 = smem_u32(sH)  + (uint32_t)(((((lane & 7) + 8 * ((lane >> 3) & 1)) * SH) + n0b + 8 * (lane >> 4)) * 2);
        #pragma unroll
        for (int kk = 0; kk < 8; kk++) {
            uint32_t a2r[4];
            ldsm4(a2r, aB2 + (uint32_t)(16 * kk * 2));
            uint32_t r0, r1, r2, r3;
            ldsm4t(r0, r1, r2, r3, bB2 + (uint32_t)(16 * kk * SH * 2));
            mma16816(acc2[0], a2r, r0, r1);
            mma16816(acc2[1], a2r, r2, r3);
        }
        const float bb0 = __ldg(b2 + gid);
        const float bb1 = __ldg(b2 + gid + 8);
        #pragma unroll
        for (int s = 0; s < 2; s++) {
            const int colb = n0b + 8 * s + 2 * tig;
            sA[gid * SAS + colb]           = softplus_f(acc2[s][0] + bb0);
            sA[gid * SAS + colb + 1]       = softplus_f(acc2[s][1] + bb0);
            sA[(gid + 8) * SAS + colb]     = softplus_f(acc2[s][2] + bb1);
            sA[(gid + 8) * SAS + colb + 1] = softplus_f(acc2[s][3] + bb1);
        }
    }
    __syncthreads();

    // write C-scaled A tile coalesced: g_A[n][a][px] = C * A
    {
        float* Ag = g_A + (size_t)n * NATT * HW + p0;
        #pragma unroll
        for (int i = tid; i < NATT * BP; i += 256) {
            int a = i >> 6, p = i & 63;
            Ag[(size_t)a * HW + p] = CSCALE * sA[a * SAS + p];
        }
    }
}

// ---------------- kernel 2: attractor update, f16x2 packed, grid=1024 ----------------
__global__ void __launch_bounds__(256)
zoe_attractor_kernel(const float* __restrict__ b_prev, float* __restrict__ out) {
    // PDL: dispatched during the MLP's last wave; block here until MLP grid
    // (and thus all g_A writes) completes.
    asm volatile("griddepcontrol.wait;" ::: "memory");

    const int blk = blockIdx.x;          // 1024 blocks: 128-px tile x 32-bin half
    const int n   = blk >> 8;
    const int t   = (blk >> 1) & 127;    // pixel tile
    const int h   = blk & 1;             // bin half: [32h, 32h+32)
    const int p0  = t * 128;
    const int pr  = threadIdx.x & 63;    // pixel pair within tile
    const int q   = threadIdx.x >> 6;    // 8-bin group within half
    const int px  = p0 + 2 * pr;

    // pre-negated C*A pairs as packed f32x2
    const float2* Ap = (const float2*)(g_A + (size_t)n * NATT * HW + px);
    uint64_t an[NATT];
    #pragma unroll
    for (int a = 0; a < NATT; a++) {
        float2 v = __ldg(Ap + (size_t)a * (HW / 2));
        an[a] = pack_f2(-v.x, -v.y);
    }
    const uint64_t C2 = pack_f2(CSCALE, CSCALE);

    const size_t base = ((size_t)n * NBIN + h * 32 + q * 8) * HW + px;
    const float2* bp = (const float2*)(b_prev + base);
    float2* o1 = (float2*)(out + base);
    float2* o2 = (float2*)(out + base + (size_t)NIMG * NBIN * HW);
    const __half2 zero2 = __floats2half2_rn(0.0f, 0.0f);

    #pragma unroll 2
    for (int j = 0; j < 8; j++) {
        const size_t off = (size_t)j * (HW / 2);
        const float2 b = __ldg(bp + off);
        const uint64_t cb2 = mulx2(pack_f2(b.x, b.y), C2);   // (C*b0, C*b1)

        __half2 accA = zero2;
        __half2 accB = zero2;
        #pragma unroll
        for (int a = 0; a < NATT; a += 2) {
            {
                uint64_t m = addx2(cb2, an[a]);              // m = C*(b - A) = -C*dx
                float mlo, mhi; unpack_f2(m, mlo, mhi);
                __half2 h2 = __floats2half2_rn(mlo, mhi);
                __half2 y2 = __hfma2(h2, __hneg2(h2), zero2); // -(C*dx)^2
                uint32_t uy = *(uint32_t*)&y2, ue;
                asm("ex2.approx.f16x2 %0, %1;" : "=r"(ue) : "r"(uy));
                accA = __hfma2(*(__half2*)&ue, h2, accA);     // accumulates e * (-C*dx)
            }
            {
                uint64_t m = addx2(cb2, an[a + 1]);
                float mlo, mhi; unpack_f2(m, mlo, mhi);
                __half2 h2 = __floats2half2_rn(mlo, mhi);
                __half2 y2 = __hfma2(h2, __hneg2(h2), zero2);
                uint32_t uy = *(uint32_t*)&y2, ue;
                asm("ex2.approx.f16x2 %0, %1;" : "=r"(ue) : "r"(uy));
                accB = __hfma2(*(__half2*)&ue, h2, accB);
            }
        }
        float s0 = __low2float(accA)  + __low2float(accB);
        float s1 = __high2float(accA) + __high2float(accB);
        float2 dv;
        dv.x = fmaf(s0, -INVC, b.x);   // delta = -(1/C) * sum(e * (-C*dx))
        dv.y = fmaf(s1, -INVC, b.y);
        o1[off] = dv;
        o2[off] = dv;
    }
}

extern "C" void kernel_launch(void* const* d_in, const int* in_sizes, int n_in,
                              void* d_out, int out_size) {
    const float* x      = (const float*)d_in[0];
    const float* b_prev = (const float*)d_in[1];
    const float* w1     = (const float*)d_in[2];
    const float* b1     = (const float*)d_in[3];
    const float* w2     = (const float*)d_in[4];
    const float* b2     = (const float*)d_in[5];
    float* out = (float*)d_out;

    const int ntot = NX4Q + NW1 + NW2;
    convert_inputs<<<(ntot + 255) / 256, 256>>>(x, w1, w2);

    cudaFuncSetAttribute(zoe_mlp_kernel,
                         cudaFuncAttributeMaxDynamicSharedMemorySize, SMEM_TOTAL);

    cudaLaunchAttribute pdl;
    pdl.id = cudaLaunchAttributeProgrammaticStreamSerialization;
    pdl.val.programmaticStreamSerializationAllowed = 1;

    cudaLaunchConfig_t cfg1 = {};
    cfg1.gridDim = dim3(NIMG * (HW / BP));
    cfg1.blockDim = dim3(256);
    cfg1.dynamicSmemBytes = SMEM_TOTAL;
    cfg1.stream = 0;
    cfg1.attrs = &pdl;
    cfg1.numAttrs = 1;
    cudaLaunchKernelEx(&cfg1, zoe_mlp_kernel, b1, b2);

    cudaLaunchConfig_t cfg2 = {};
    cfg2.gridDim = dim3(NIMG * 256);
    cfg2.blockDim = dim3(256);
    cfg2.stream = 0;
    cfg2.attrs = &pdl;
    cfg2.numAttrs = 1;
    cudaLaunchKernelEx(&cfg2, zoe_attractor_kernel, b_prev, out);
}